// round 1
// baseline (speedup 1.0000x reference)
#include <cuda_runtime.h>
#include <math.h>

// Problem constants
#define B 64
#define S 4096
#define H 256
#define CHUNKS 16
#define ROWS_PER_CHUNK (S / CHUNKS)   // 256
#define WARPS 8
#define ROWS_PER_WARP (ROWS_PER_CHUNK / WARPS)  // 32
#define NEGC 1e30f

// Scratch: per (b, chunk): 256 acc + m + l  (padded to 258 floats)
__device__ float g_scratch[B * CHUNKS * (H + 2)];

// ---------------------------------------------------------------------------
// Kernel 1: streaming online-softmax partials.
// grid = (CHUNKS, B), block = 256 (8 warps). Each warp handles 32 rows of S.
// Each lane owns 8 contiguous h-elements (two float4 per row).
// ---------------------------------------------------------------------------
__global__ void __launch_bounds__(256, 4)
attn_partial_kernel(const float* __restrict__ inp,
                    const float* __restrict__ mask,
                    const float* __restrict__ query)
{
    const int chunk = blockIdx.x;
    const int b     = blockIdx.y;
    const int tid   = threadIdx.x;
    const int w     = tid >> 5;
    const int lane  = tid & 31;

    // Per-lane query slice (8 floats)
    float q[8];
    {
        const float4* qp = reinterpret_cast<const float4*>(query + (size_t)b * H + lane * 8);
        float4 q0 = qp[0], q1 = qp[1];
        q[0]=q0.x; q[1]=q0.y; q[2]=q0.z; q[3]=q0.w;
        q[4]=q1.x; q[5]=q1.y; q[6]=q1.z; q[7]=q1.w;
    }

    float m = -3.0e38f;
    float l = 0.0f;
    float acc[8];
    #pragma unroll
    for (int i = 0; i < 8; i++) acc[i] = 0.0f;

    const int s_base = chunk * ROWS_PER_CHUNK + w * ROWS_PER_WARP;
    const float* row  = inp  + ((size_t)b * S + s_base) * H + lane * 8;
    const float* mrow = mask + (size_t)b * S + s_base;

    #pragma unroll 2
    for (int r = 0; r < ROWS_PER_WARP; r++) {
        const float4 v0 = *reinterpret_cast<const float4*>(row);
        const float4 v1 = *reinterpret_cast<const float4*>(row + 4);
        const float mk  = mrow[r];

        float dot = q[0]*v0.x + q[1]*v0.y + q[2]*v0.z + q[3]*v0.w
                  + q[4]*v1.x + q[5]*v1.y + q[6]*v1.z + q[7]*v1.w;
        // warp reduce (sum over h)
        #pragma unroll
        for (int off = 16; off > 0; off >>= 1)
            dot += __shfl_xor_sync(0xffffffffu, dot, off);

        const float sc = dot - NEGC * (1.0f - mk);
        const float mn = fmaxf(m, sc);
        const float alpha = __expf(m - mn);
        const float p     = __expf(sc - mn);
        l = l * alpha + p;
        acc[0] = acc[0]*alpha + p*v0.x;
        acc[1] = acc[1]*alpha + p*v0.y;
        acc[2] = acc[2]*alpha + p*v0.z;
        acc[3] = acc[3]*alpha + p*v0.w;
        acc[4] = acc[4]*alpha + p*v1.x;
        acc[5] = acc[5]*alpha + p*v1.y;
        acc[6] = acc[6]*alpha + p*v1.z;
        acc[7] = acc[7]*alpha + p*v1.w;
        m = mn;
        row += H;
    }

    // Block-level combine of the 8 warp partials.
    __shared__ float sm_m[WARPS];
    __shared__ float sm_l[WARPS];
    __shared__ float sm_acc[WARPS * H];

    if (lane == 0) { sm_m[w] = m; sm_l[w] = l; }
    #pragma unroll
    for (int i = 0; i < 8; i++)
        sm_acc[w * H + lane * 8 + i] = acc[i];
    __syncthreads();

    // thread tid owns output element h = tid
    float mb = sm_m[0];
    #pragma unroll
    for (int ww = 1; ww < WARPS; ww++) mb = fmaxf(mb, sm_m[ww]);

    float lb = 0.0f, ab = 0.0f;
    #pragma unroll
    for (int ww = 0; ww < WARPS; ww++) {
        const float e = __expf(sm_m[ww] - mb);
        lb += sm_l[ww] * e;
        ab += sm_acc[ww * H + tid] * e;
    }

    float* dst = g_scratch + ((size_t)(b * CHUNKS + chunk)) * (H + 2);
    dst[tid] = ab;
    if (tid == 0) { dst[H] = mb; dst[H + 1] = lb; }
}

// ---------------------------------------------------------------------------
// Kernel 2: combine 16 chunk-partials per batch -> extracted_msg (out[0:B*H]).
// grid = B, block = 256.
// ---------------------------------------------------------------------------
__global__ void __launch_bounds__(256)
attn_combine_kernel(float* __restrict__ out)
{
    const int b = blockIdx.x;
    const int h = threadIdx.x;

    const float* base = g_scratch + (size_t)b * CHUNKS * (H + 2);

    float ms[CHUNKS];
    float m = -3.0e38f;
    #pragma unroll
    for (int c = 0; c < CHUNKS; c++) {
        ms[c] = base[c * (H + 2) + H];
        m = fmaxf(m, ms[c]);
    }

    float l = 0.0f, a = 0.0f;
    #pragma unroll
    for (int c = 0; c < CHUNKS; c++) {
        const float e = __expf(ms[c] - m);
        l += base[c * (H + 2) + H + 1] * e;
        a += base[c * (H + 2) + h] * e;
    }

    out[(size_t)b * H + h] = a / l;
}

// ---------------------------------------------------------------------------
// Kernel 3: control_emb = concat(query, extracted) @ W^T + bias.
// grid = B, block = 256. W is [H, 2H] row-major; row j is 512 contiguous f32.
// ---------------------------------------------------------------------------
__global__ void __launch_bounds__(256)
proj_kernel(const float* __restrict__ query,
            const float* __restrict__ W,
            const float* __restrict__ bias,
            float* __restrict__ out)   // out base = d_out
{
    const int b = blockIdx.x;
    const int j = threadIdx.x;

    __shared__ float conc[2 * H];
    conc[j]     = query[(size_t)b * H + j];
    conc[H + j] = out[(size_t)b * H + j];   // extracted_msg written by kernel 2
    __syncthreads();

    const float4* wr = reinterpret_cast<const float4*>(W + (size_t)j * (2 * H));
    float s = bias[j];
    #pragma unroll 8
    for (int k = 0; k < (2 * H) / 4; k++) {
        const float4 wv = wr[k];
        s += wv.x * conc[4*k + 0] + wv.y * conc[4*k + 1]
           + wv.z * conc[4*k + 2] + wv.w * conc[4*k + 3];
    }

    out[(size_t)B * H + (size_t)b * H + j] = s;
}

// ---------------------------------------------------------------------------
// Launch
// ---------------------------------------------------------------------------
extern "C" void kernel_launch(void* const* d_in, const int* in_sizes, int n_in,
                              void* d_out, int out_size)
{
    const float* inp_seq = (const float*)d_in[0];  // [B,S,H]
    const float* mask    = (const float*)d_in[1];  // [B,S]
    const float* query   = (const float*)d_in[2];  // [B,H]
    const float* W       = (const float*)d_in[3];  // [H,2H]
    const float* bias    = (const float*)d_in[4];  // [H]
    float* out = (float*)d_out;                    // [B*H extracted | B*H control]

    dim3 grid1(CHUNKS, B);
    attn_partial_kernel<<<grid1, 256>>>(inp_seq, mask, query);
    attn_combine_kernel<<<B, 256>>>(out);
    proj_kernel<<<B, 256>>>(query, W, bias, out);
}

// round 2
// speedup vs baseline: 1.0625x; 1.0625x over previous
#include <cuda_runtime.h>
#include <math.h>

// Problem constants
#define B 64
#define S 4096
#define H 256
#define CHUNKS 8
#define ROWS_PER_CHUNK (S / CHUNKS)             // 512
#define WARPS 8
#define ROWS_PER_WARP (ROWS_PER_CHUNK / WARPS)  // 64
#define NEGC 1e30f

// Scratch: per (b, chunk): 256 acc + m + l (258 floats)
__device__ float g_scratch[B * CHUNKS * (H + 2)];

// ---------------------------------------------------------------------------
// Kernel 1: streaming online-softmax partials.
// grid = (CHUNKS, B) = 512 CTAs -> single wave at occ 4.
// block = 256 (8 warps). Each warp handles 64 rows, processed 2 at a time:
// doubled load MLP, interleaved shfl-reduce chains, merged rescale.
// ---------------------------------------------------------------------------
__global__ void __launch_bounds__(256, 4)
attn_partial_kernel(const float* __restrict__ inp,
                    const float* __restrict__ mask,
                    const float* __restrict__ query)
{
    const int chunk = blockIdx.x;
    const int b     = blockIdx.y;
    const int tid   = threadIdx.x;
    const int w     = tid >> 5;
    const int lane  = tid & 31;

    // Per-lane query slice (8 floats)
    float q[8];
    {
        const float4* qp = reinterpret_cast<const float4*>(query + (size_t)b * H + lane * 8);
        float4 q0 = qp[0], q1 = qp[1];
        q[0]=q0.x; q[1]=q0.y; q[2]=q0.z; q[3]=q0.w;
        q[4]=q1.x; q[5]=q1.y; q[6]=q1.z; q[7]=q1.w;
    }

    float m = -3.0e38f;
    float l = 0.0f;
    float acc[8];
    #pragma unroll
    for (int i = 0; i < 8; i++) acc[i] = 0.0f;

    const int s_base = chunk * ROWS_PER_CHUNK + w * ROWS_PER_WARP;
    const float* row  = inp  + ((size_t)b * S + s_base) * H + lane * 8;
    const float* mrow = mask + (size_t)b * S + s_base;

    for (int r = 0; r < ROWS_PER_WARP; r += 2) {
        // Row r
        const float4 a0 = *reinterpret_cast<const float4*>(row);
        const float4 a1 = *reinterpret_cast<const float4*>(row + 4);
        // Row r+1
        const float4 c0 = *reinterpret_cast<const float4*>(row + H);
        const float4 c1 = *reinterpret_cast<const float4*>(row + H + 4);
        const float mk0 = mrow[r];
        const float mk1 = mrow[r + 1];

        float d0 = q[0]*a0.x + q[1]*a0.y + q[2]*a0.z + q[3]*a0.w
                 + q[4]*a1.x + q[5]*a1.y + q[6]*a1.z + q[7]*a1.w;
        float d1 = q[0]*c0.x + q[1]*c0.y + q[2]*c0.z + q[3]*c0.w
                 + q[4]*c1.x + q[5]*c1.y + q[6]*c1.z + q[7]*c1.w;

        // Two independent butterfly reductions, interleaved
        #pragma unroll
        for (int off = 16; off > 0; off >>= 1) {
            d0 += __shfl_xor_sync(0xffffffffu, d0, off);
            d1 += __shfl_xor_sync(0xffffffffu, d1, off);
        }

        const float sc0 = d0 - NEGC * (1.0f - mk0);
        const float sc1 = d1 - NEGC * (1.0f - mk1);
        const float mn  = fmaxf(m, fmaxf(sc0, sc1));
        const float alpha = __expf(m  - mn);
        const float p0    = __expf(sc0 - mn);
        const float p1    = __expf(sc1 - mn);
        l = l * alpha + p0 + p1;
        acc[0] = acc[0]*alpha + p0*a0.x + p1*c0.x;
        acc[1] = acc[1]*alpha + p0*a0.y + p1*c0.y;
        acc[2] = acc[2]*alpha + p0*a0.z + p1*c0.z;
        acc[3] = acc[3]*alpha + p0*a0.w + p1*c0.w;
        acc[4] = acc[4]*alpha + p0*a1.x + p1*c1.x;
        acc[5] = acc[5]*alpha + p0*a1.y + p1*c1.y;
        acc[6] = acc[6]*alpha + p0*a1.z + p1*c1.z;
        acc[7] = acc[7]*alpha + p0*a1.w + p1*c1.w;
        m = mn;
        row += 2 * H;
    }

    // Block-level combine of 8 warp partials.
    __shared__ float sm_m[WARPS];
    __shared__ float sm_l[WARPS];
    __shared__ float sm_acc[WARPS * H];

    if (lane == 0) { sm_m[w] = m; sm_l[w] = l; }
    #pragma unroll
    for (int i = 0; i < 8; i++)
        sm_acc[w * H + lane * 8 + i] = acc[i];
    __syncthreads();

    float mb = sm_m[0];
    #pragma unroll
    for (int ww = 1; ww < WARPS; ww++) mb = fmaxf(mb, sm_m[ww]);

    float lb = 0.0f, ab = 0.0f;
    #pragma unroll
    for (int ww = 0; ww < WARPS; ww++) {
        const float e = __expf(sm_m[ww] - mb);
        lb += sm_l[ww] * e;
        ab += sm_acc[ww * H + tid] * e;
    }

    float* dst = g_scratch + ((size_t)(b * CHUNKS + chunk)) * (H + 2);
    dst[tid] = ab;
    if (tid == 0) { dst[H] = mb; dst[H + 1] = lb; }
}

// ---------------------------------------------------------------------------
// Kernel 2 (fused tail): combine chunk partials -> extracted_msg, then
// control_emb = concat(query, extracted) @ W^T + bias. grid = B, block = 256.
// ---------------------------------------------------------------------------
__global__ void __launch_bounds__(256)
combine_proj_kernel(const float* __restrict__ query,
                    const float* __restrict__ W,
                    const float* __restrict__ bias,
                    float* __restrict__ out)
{
    const int b = blockIdx.x;
    const int t = threadIdx.x;   // doubles as h-index and output-j index

    __shared__ float conc[2 * H];

    // --- combine partials for element h = t ---
    const float* base = g_scratch + (size_t)b * CHUNKS * (H + 2);

    float ms[CHUNKS];
    float m = -3.0e38f;
    #pragma unroll
    for (int c = 0; c < CHUNKS; c++) {
        ms[c] = base[c * (H + 2) + H];
        m = fmaxf(m, ms[c]);
    }

    float l = 0.0f, a = 0.0f;
    #pragma unroll
    for (int c = 0; c < CHUNKS; c++) {
        const float e = __expf(ms[c] - m);
        l += base[c * (H + 2) + H + 1] * e;
        a += base[c * (H + 2) + t] * e;
    }

    const float ext = a / l;
    out[(size_t)b * H + t] = ext;           // extracted_msg
    conc[t]     = query[(size_t)b * H + t];
    conc[H + t] = ext;
    __syncthreads();

    // --- projection: out_j = bias_j + sum_k W[j,k] * conc[k] ---
    const float4* wr = reinterpret_cast<const float4*>(W + (size_t)t * (2 * H));
    float s = bias[t];
    #pragma unroll 8
    for (int k = 0; k < (2 * H) / 4; k++) {
        const float4 wv = wr[k];
        s += wv.x * conc[4*k + 0] + wv.y * conc[4*k + 1]
           + wv.z * conc[4*k + 2] + wv.w * conc[4*k + 3];
    }

    out[(size_t)B * H + (size_t)b * H + t] = s;
}

// ---------------------------------------------------------------------------
// Launch
// ---------------------------------------------------------------------------
extern "C" void kernel_launch(void* const* d_in, const int* in_sizes, int n_in,
                              void* d_out, int out_size)
{
    const float* inp_seq = (const float*)d_in[0];  // [B,S,H]
    const float* mask    = (const float*)d_in[1];  // [B,S]
    const float* query   = (const float*)d_in[2];  // [B,H]
    const float* W       = (const float*)d_in[3];  // [H,2H]
    const float* bias    = (const float*)d_in[4];  // [H]
    float* out = (float*)d_out;                    // [B*H extracted | B*H control]

    dim3 grid1(CHUNKS, B);
    attn_partial_kernel<<<grid1, 256>>>(inp_seq, mask, query);
    combine_proj_kernel<<<B, 256>>>(query, W, bias, out);
}

// round 3
// speedup vs baseline: 1.2977x; 1.2213x over previous
#include <cuda_runtime.h>
#include <math.h>

// Problem constants
#define B 64
#define S 4096
#define H 256
#define CHUNKS 8
#define ROWS_PER_CHUNK (S / CHUNKS)             // 512
#define WARPS 8
#define ROWS_PER_WARP (ROWS_PER_CHUNK / WARPS)  // 64
#define NEGC 1e30f

// Scratch: per (b, chunk): 256 acc + m + l (258 floats)
__device__ float g_scratch[B * CHUNKS * (H + 2)];

// ---------------------------------------------------------------------------
// Kernel 1: streaming online-softmax partials. (unchanged from R2: HBM-bound)
// grid = (CHUNKS, B) = 512 CTAs, block = 256 (8 warps).
// ---------------------------------------------------------------------------
__global__ void __launch_bounds__(256, 4)
attn_partial_kernel(const float* __restrict__ inp,
                    const float* __restrict__ mask,
                    const float* __restrict__ query)
{
    const int chunk = blockIdx.x;
    const int b     = blockIdx.y;
    const int tid   = threadIdx.x;
    const int w     = tid >> 5;
    const int lane  = tid & 31;

    float q[8];
    {
        const float4* qp = reinterpret_cast<const float4*>(query + (size_t)b * H + lane * 8);
        float4 q0 = qp[0], q1 = qp[1];
        q[0]=q0.x; q[1]=q0.y; q[2]=q0.z; q[3]=q0.w;
        q[4]=q1.x; q[5]=q1.y; q[6]=q1.z; q[7]=q1.w;
    }

    float m = -3.0e38f;
    float l = 0.0f;
    float acc[8];
    #pragma unroll
    for (int i = 0; i < 8; i++) acc[i] = 0.0f;

    const int s_base = chunk * ROWS_PER_CHUNK + w * ROWS_PER_WARP;
    const float* row  = inp  + ((size_t)b * S + s_base) * H + lane * 8;
    const float* mrow = mask + (size_t)b * S + s_base;

    for (int r = 0; r < ROWS_PER_WARP; r += 2) {
        const float4 a0 = *reinterpret_cast<const float4*>(row);
        const float4 a1 = *reinterpret_cast<const float4*>(row + 4);
        const float4 c0 = *reinterpret_cast<const float4*>(row + H);
        const float4 c1 = *reinterpret_cast<const float4*>(row + H + 4);
        const float mk0 = mrow[r];
        const float mk1 = mrow[r + 1];

        float d0 = q[0]*a0.x + q[1]*a0.y + q[2]*a0.z + q[3]*a0.w
                 + q[4]*a1.x + q[5]*a1.y + q[6]*a1.z + q[7]*a1.w;
        float d1 = q[0]*c0.x + q[1]*c0.y + q[2]*c0.z + q[3]*c0.w
                 + q[4]*c1.x + q[5]*c1.y + q[6]*c1.z + q[7]*c1.w;

        #pragma unroll
        for (int off = 16; off > 0; off >>= 1) {
            d0 += __shfl_xor_sync(0xffffffffu, d0, off);
            d1 += __shfl_xor_sync(0xffffffffu, d1, off);
        }

        const float sc0 = d0 - NEGC * (1.0f - mk0);
        const float sc1 = d1 - NEGC * (1.0f - mk1);
        const float mn  = fmaxf(m, fmaxf(sc0, sc1));
        const float alpha = __expf(m  - mn);
        const float p0    = __expf(sc0 - mn);
        const float p1    = __expf(sc1 - mn);
        l = l * alpha + p0 + p1;
        acc[0] = acc[0]*alpha + p0*a0.x + p1*c0.x;
        acc[1] = acc[1]*alpha + p0*a0.y + p1*c0.y;
        acc[2] = acc[2]*alpha + p0*a0.z + p1*c0.z;
        acc[3] = acc[3]*alpha + p0*a0.w + p1*c0.w;
        acc[4] = acc[4]*alpha + p0*a1.x + p1*c1.x;
        acc[5] = acc[5]*alpha + p0*a1.y + p1*c1.y;
        acc[6] = acc[6]*alpha + p0*a1.z + p1*c1.z;
        acc[7] = acc[7]*alpha + p0*a1.w + p1*c1.w;
        m = mn;
        row += 2 * H;
    }

    __shared__ float sm_m[WARPS];
    __shared__ float sm_l[WARPS];
    __shared__ float sm_acc[WARPS * H];

    if (lane == 0) { sm_m[w] = m; sm_l[w] = l; }
    #pragma unroll
    for (int i = 0; i < 8; i++)
        sm_acc[w * H + lane * 8 + i] = acc[i];
    __syncthreads();

    float mb = sm_m[0];
    #pragma unroll
    for (int ww = 1; ww < WARPS; ww++) mb = fmaxf(mb, sm_m[ww]);

    float lb = 0.0f, ab = 0.0f;
    #pragma unroll
    for (int ww = 0; ww < WARPS; ww++) {
        const float e = __expf(sm_m[ww] - mb);
        lb += sm_l[ww] * e;
        ab += sm_acc[ww * H + tid] * e;
    }

    float* dst = g_scratch + ((size_t)(b * CHUNKS + chunk)) * (H + 2);
    dst[tid] = ab;
    if (tid == 0) { dst[H] = mb; dst[H + 1] = lb; }
}

// ---------------------------------------------------------------------------
// Kernel 2: fused combine + projection, warp-per-output.
// grid = (B, 4) = 256 CTAs, block = 256.
// Phase A: every CTA computes extracted_msg (redundant x4, scratch L2-hot).
// Phase B: CTA (b, by) computes outputs j in [by*64, by*64+64); each warp
// does 8 j's, lanes read W row j contiguously (coalesced), shfl-reduce.
// ---------------------------------------------------------------------------
__global__ void __launch_bounds__(256)
combine_proj_kernel(const float* __restrict__ query,
                    const float* __restrict__ W,
                    const float* __restrict__ bias,
                    float* __restrict__ out)
{
    const int b    = blockIdx.x;
    const int by   = blockIdx.y;
    const int t    = threadIdx.x;
    const int w    = t >> 5;
    const int lane = t & 31;

    __shared__ float conc[2 * H];

    // --- Phase A: combine partials for element h = t ---
    const float* base = g_scratch + (size_t)b * CHUNKS * (H + 2);

    float ms[CHUNKS];
    float m = -3.0e38f;
    #pragma unroll
    for (int c = 0; c < CHUNKS; c++) {
        ms[c] = base[c * (H + 2) + H];
        m = fmaxf(m, ms[c]);
    }

    float l = 0.0f, a = 0.0f;
    #pragma unroll
    for (int c = 0; c < CHUNKS; c++) {
        const float e = __expf(ms[c] - m);
        l += base[c * (H + 2) + H + 1] * e;
        a += base[c * (H + 2) + t] * e;
    }

    const float ext = a / l;
    if (by == 0) out[(size_t)b * H + t] = ext;   // extracted_msg (once)
    conc[t]     = query[(size_t)b * H + t];
    conc[H + t] = ext;
    __syncthreads();

    // --- Phase B: warp-per-output j. 2-way unrolled over the warp's 8 j's ---
    const int j_base = by * 64 + w * 8;

    #pragma unroll
    for (int jj = 0; jj < 8; jj += 2) {
        const int j0 = j_base + jj;
        const int j1 = j_base + jj + 1;
        const float4* w0 = reinterpret_cast<const float4*>(W + (size_t)j0 * (2 * H)) + lane;
        const float4* w1 = reinterpret_cast<const float4*>(W + (size_t)j1 * (2 * H)) + lane;

        float s0 = 0.0f, s1 = 0.0f;
        #pragma unroll
        for (int k = 0; k < 4; k++) {
            const float4 wv0 = w0[k * 32];
            const float4 wv1 = w1[k * 32];
            const float4 cv  = *reinterpret_cast<const float4*>(conc + (k * 32 + lane) * 4);
            s0 += wv0.x*cv.x + wv0.y*cv.y + wv0.z*cv.z + wv0.w*cv.w;
            s1 += wv1.x*cv.x + wv1.y*cv.y + wv1.z*cv.z + wv1.w*cv.w;
        }
        #pragma unroll
        for (int off = 16; off > 0; off >>= 1) {
            s0 += __shfl_xor_sync(0xffffffffu, s0, off);
            s1 += __shfl_xor_sync(0xffffffffu, s1, off);
        }
        if (lane == 0) {
            out[(size_t)B * H + (size_t)b * H + j0] = s0 + bias[j0];
            out[(size_t)B * H + (size_t)b * H + j1] = s1 + bias[j1];
        }
    }
}

// ---------------------------------------------------------------------------
// Launch
// ---------------------------------------------------------------------------
extern "C" void kernel_launch(void* const* d_in, const int* in_sizes, int n_in,
                              void* d_out, int out_size)
{
    const float* inp_seq = (const float*)d_in[0];  // [B,S,H]
    const float* mask    = (const float*)d_in[1];  // [B,S]
    const float* query   = (const float*)d_in[2];  // [B,H]
    const float* W       = (const float*)d_in[3];  // [H,2H]
    const float* bias    = (const float*)d_in[4];  // [H]
    float* out = (float*)d_out;                    // [B*H extracted | B*H control]

    dim3 grid1(CHUNKS, B);
    attn_partial_kernel<<<grid1, 256>>>(inp_seq, mask, query);
    dim3 grid2(B, 4);
    combine_proj_kernel<<<grid2, 256>>>(query, W, bias, out);
}

// round 4
// speedup vs baseline: 1.3333x; 1.0275x over previous
#include <cuda_runtime.h>
#include <math.h>

// Problem constants
#define B 64
#define S 4096
#define H 256
#define CHUNKS 16
#define ROWS_PER_CHUNK (S / CHUNKS)             // 256
#define WARPS 4
#define ROWS_PER_WARP (ROWS_PER_CHUNK / WARPS)  // 64
#define NEGC 1e30f

// Scratch: per (b, chunk): 256 acc + m + l (258 floats)
__device__ float g_scratch[B * CHUNKS * (H + 2)];

// ---------------------------------------------------------------------------
// Kernel 1: streaming online-softmax partials.
// block = 128 (4 warps), grid = (CHUNKS, B) = 1024 CTAs.
// 1024/148 = 6.92 CTAs/SM, single wave, ~1% imbalance (vs 15% at 512 CTAs).
// ---------------------------------------------------------------------------
__global__ void __launch_bounds__(128)
attn_partial_kernel(const float* __restrict__ inp,
                    const float* __restrict__ mask,
                    const float* __restrict__ query)
{
    const int chunk = blockIdx.x;
    const int b     = blockIdx.y;
    const int tid   = threadIdx.x;
    const int w     = tid >> 5;
    const int lane  = tid & 31;

    float q[8];
    {
        const float4* qp = reinterpret_cast<const float4*>(query + (size_t)b * H + lane * 8);
        float4 q0 = qp[0], q1 = qp[1];
        q[0]=q0.x; q[1]=q0.y; q[2]=q0.z; q[3]=q0.w;
        q[4]=q1.x; q[5]=q1.y; q[6]=q1.z; q[7]=q1.w;
    }

    float m = -3.0e38f;
    float l = 0.0f;
    float acc[8];
    #pragma unroll
    for (int i = 0; i < 8; i++) acc[i] = 0.0f;

    const int s_base = chunk * ROWS_PER_CHUNK + w * ROWS_PER_WARP;
    const float* row  = inp  + ((size_t)b * S + s_base) * H + lane * 8;
    const float* mrow = mask + (size_t)b * S + s_base;

    for (int r = 0; r < ROWS_PER_WARP; r += 2) {
        const float4 a0 = *reinterpret_cast<const float4*>(row);
        const float4 a1 = *reinterpret_cast<const float4*>(row + 4);
        const float4 c0 = *reinterpret_cast<const float4*>(row + H);
        const float4 c1 = *reinterpret_cast<const float4*>(row + H + 4);
        const float mk0 = mrow[r];
        const float mk1 = mrow[r + 1];

        float d0 = q[0]*a0.x + q[1]*a0.y + q[2]*a0.z + q[3]*a0.w
                 + q[4]*a1.x + q[5]*a1.y + q[6]*a1.z + q[7]*a1.w;
        float d1 = q[0]*c0.x + q[1]*c0.y + q[2]*c0.z + q[3]*c0.w
                 + q[4]*c1.x + q[5]*c1.y + q[6]*c1.z + q[7]*c1.w;

        #pragma unroll
        for (int off = 16; off > 0; off >>= 1) {
            d0 += __shfl_xor_sync(0xffffffffu, d0, off);
            d1 += __shfl_xor_sync(0xffffffffu, d1, off);
        }

        const float sc0 = d0 - NEGC * (1.0f - mk0);
        const float sc1 = d1 - NEGC * (1.0f - mk1);
        const float mn  = fmaxf(m, fmaxf(sc0, sc1));
        const float alpha = __expf(m  - mn);
        const float p0    = __expf(sc0 - mn);
        const float p1    = __expf(sc1 - mn);
        l = l * alpha + p0 + p1;
        acc[0] = acc[0]*alpha + p0*a0.x + p1*c0.x;
        acc[1] = acc[1]*alpha + p0*a0.y + p1*c0.y;
        acc[2] = acc[2]*alpha + p0*a0.z + p1*c0.z;
        acc[3] = acc[3]*alpha + p0*a0.w + p1*c0.w;
        acc[4] = acc[4]*alpha + p0*a1.x + p1*c1.x;
        acc[5] = acc[5]*alpha + p0*a1.y + p1*c1.y;
        acc[6] = acc[6]*alpha + p0*a1.z + p1*c1.z;
        acc[7] = acc[7]*alpha + p0*a1.w + p1*c1.w;
        m = mn;
        row += 2 * H;
    }

    // Block-level combine of 4 warp partials. Each thread outputs h=tid, h=tid+128.
    __shared__ float sm_m[WARPS];
    __shared__ float sm_l[WARPS];
    __shared__ float sm_acc[WARPS * H];

    if (lane == 0) { sm_m[w] = m; sm_l[w] = l; }
    #pragma unroll
    for (int i = 0; i < 8; i++)
        sm_acc[w * H + lane * 8 + i] = acc[i];
    __syncthreads();

    float mb = sm_m[0];
    #pragma unroll
    for (int ww = 1; ww < WARPS; ww++) mb = fmaxf(mb, sm_m[ww]);

    float lb = 0.0f, ab0 = 0.0f, ab1 = 0.0f;
    #pragma unroll
    for (int ww = 0; ww < WARPS; ww++) {
        const float e = __expf(sm_m[ww] - mb);
        lb  += sm_l[ww] * e;
        ab0 += sm_acc[ww * H + tid] * e;
        ab1 += sm_acc[ww * H + tid + 128] * e;
    }

    float* dst = g_scratch + ((size_t)(b * CHUNKS + chunk)) * (H + 2);
    dst[tid]       = ab0;
    dst[tid + 128] = ab1;
    if (tid == 0) { dst[H] = mb; dst[H + 1] = lb; }
}

// ---------------------------------------------------------------------------
// Kernel 2: fused combine + projection, warp-per-output.
// grid = (B, 8) = 512 CTAs, block = 256 (8 warps).
// Phase A: every CTA computes extracted_msg (redundant x8, scratch L2-hot).
// Phase B: CTA (b, by) computes j in [by*32, by*32+32); each warp does 4 j's.
// ---------------------------------------------------------------------------
__global__ void __launch_bounds__(256)
combine_proj_kernel(const float* __restrict__ query,
                    const float* __restrict__ W,
                    const float* __restrict__ bias,
                    float* __restrict__ out)
{
    const int b    = blockIdx.x;
    const int by   = blockIdx.y;
    const int t    = threadIdx.x;
    const int w    = t >> 5;
    const int lane = t & 31;

    __shared__ float conc[2 * H];

    // --- Phase A: combine partials for element h = t ---
    const float* base = g_scratch + (size_t)b * CHUNKS * (H + 2);

    float ms[CHUNKS];
    float m = -3.0e38f;
    #pragma unroll
    for (int c = 0; c < CHUNKS; c++) {
        ms[c] = base[c * (H + 2) + H];
        m = fmaxf(m, ms[c]);
    }

    float l = 0.0f, a = 0.0f;
    #pragma unroll
    for (int c = 0; c < CHUNKS; c++) {
        const float e = __expf(ms[c] - m);
        l += base[c * (H + 2) + H + 1] * e;
        a += base[c * (H + 2) + t] * e;
    }

    const float ext = a / l;
    if (by == 0) out[(size_t)b * H + t] = ext;   // extracted_msg (once)
    conc[t]     = query[(size_t)b * H + t];
    conc[H + t] = ext;
    __syncthreads();

    // --- Phase B: warp computes 4 outputs, coalesced W reads, shfl-reduce ---
    const int j_base = by * 32 + w * 4;

    #pragma unroll
    for (int jj = 0; jj < 4; jj += 2) {
        const int j0 = j_base + jj;
        const int j1 = j_base + jj + 1;
        const float4* w0 = reinterpret_cast<const float4*>(W + (size_t)j0 * (2 * H)) + lane;
        const float4* w1 = reinterpret_cast<const float4*>(W + (size_t)j1 * (2 * H)) + lane;

        float s0 = 0.0f, s1 = 0.0f;
        #pragma unroll
        for (int k = 0; k < 4; k++) {
            const float4 wv0 = w0[k * 32];
            const float4 wv1 = w1[k * 32];
            const float4 cv  = *reinterpret_cast<const float4*>(conc + (k * 32 + lane) * 4);
            s0 += wv0.x*cv.x + wv0.y*cv.y + wv0.z*cv.z + wv0.w*cv.w;
            s1 += wv1.x*cv.x + wv1.y*cv.y + wv1.z*cv.z + wv1.w*cv.w;
        }
        #pragma unroll
        for (int off = 16; off > 0; off >>= 1) {
            s0 += __shfl_xor_sync(0xffffffffu, s0, off);
            s1 += __shfl_xor_sync(0xffffffffu, s1, off);
        }
        if (lane == 0) {
            out[(size_t)B * H + (size_t)b * H + j0] = s0 + bias[j0];
            out[(size_t)B * H + (size_t)b * H + j1] = s1 + bias[j1];
        }
    }
}

// ---------------------------------------------------------------------------
// Launch
// ---------------------------------------------------------------------------
extern "C" void kernel_launch(void* const* d_in, const int* in_sizes, int n_in,
                              void* d_out, int out_size)
{
    const float* inp_seq = (const float*)d_in[0];  // [B,S,H]
    const float* mask    = (const float*)d_in[1];  // [B,S]
    const float* query   = (const float*)d_in[2];  // [B,H]
    const float* W       = (const float*)d_in[3];  // [H,2H]
    const float* bias    = (const float*)d_in[4];  // [H]
    float* out = (float*)d_out;                    // [B*H extracted | B*H control]

    dim3 grid1(CHUNKS, B);
    attn_partial_kernel<<<grid1, 128>>>(inp_seq, mask, query);
    dim3 grid2(B, 8);
    combine_proj_kernel<<<grid2, 256>>>(query, W, bias, out);
}